// round 6
// baseline (speedup 1.0000x reference)
#include <cuda_runtime.h>
#include <cuda_bf16.h>
#include <cstdint>
#include <cstddef>

typedef __nv_bfloat16 bf16;

#define NN 8192
#define STAGE_BYTES 49152u
#define SMEM_BYTES (3 * 49152)

// ---------------- device scratch (no allocs allowed; zero-init at load) ----
__device__ __align__(1024) bf16 g_adj_hi[(size_t)NN * NN];
__device__ __align__(1024) bf16 g_adj_lo[(size_t)NN * NN];
__device__ __align__(1024) bf16 g_ht_hi[256 * NN];           // transposed features [F][NN]
__device__ __align__(1024) bf16 g_ht_lo[256 * NN];
__device__ __align__(1024) bf16 g_catA_hi[(size_t)NN * 512]; // layer1 concat [h|support]
__device__ __align__(1024) bf16 g_catA_lo[(size_t)NN * 512];
__device__ __align__(1024) bf16 g_catB_hi[(size_t)NN * 256]; // layers 2-4 concat
__device__ __align__(1024) bf16 g_catB_lo[(size_t)NN * 256];
__device__ __align__(1024) bf16 g_wt_hi[163840];             // W^T all 4 layers
__device__ __align__(1024) bf16 g_wt_lo[163840];

// ---------------- helpers ----------------
__device__ __forceinline__ uint32_t s2u(const void* p) {
    uint32_t a;
    asm("{ .reg .u64 t; cvta.to.shared.u64 t, %1; cvt.u32.u64 %0, t; }" : "=r"(a) : "l"(p));
    return a;
}

#define CP16(dst_u32, src_ptr) \
    asm volatile("cp.async.cg.shared.global [%0], [%1], 16;" :: "r"(dst_u32), "l"(src_ptr) : "memory")

__device__ __forceinline__ void ldsm4(uint32_t a[4], uint32_t addr) {
    asm volatile("ldmatrix.sync.aligned.m8n8.x4.shared.b16 {%0,%1,%2,%3}, [%4];"
                 : "=r"(a[0]), "=r"(a[1]), "=r"(a[2]), "=r"(a[3]) : "r"(addr));
}

__device__ __forceinline__ void mma16816(float c[4], const uint32_t a[4], const uint32_t b[2]) {
    asm volatile(
        "mma.sync.aligned.m16n8k16.row.col.f32.bf16.bf16.f32 "
        "{%0,%1,%2,%3}, {%4,%5,%6,%7}, {%8,%9}, {%0,%1,%2,%3};"
        : "+f"(c[0]), "+f"(c[1]), "+f"(c[2]), "+f"(c[3])
        : "r"(a[0]), "r"(a[1]), "r"(a[2]), "r"(a[3]), "r"(b[0]), "r"(b[1]));
}

__device__ __forceinline__ void split2(float v, bf16& h, bf16& l) {
    h = __float2bfloat16(v);
    l = __float2bfloat16(v - __bfloat162float(h));
}

__device__ __forceinline__ uint32_t pack2(float a, float b) {
    __nv_bfloat162 p = __halves2bfloat162(__float2bfloat16(a), __float2bfloat16(b));
    return *reinterpret_cast<uint32_t*>(&p);
}

// ---------------- prep kernels ----------------
// split fp32 -> bf16 hi/lo, 8 floats per thread-iter, 16B stores
__global__ void k_split(const float4* __restrict__ src, uint4* __restrict__ hi,
                        uint4* __restrict__ lo, size_t n8) {
    size_t i = (size_t)blockIdx.x * blockDim.x + threadIdx.x;
    size_t stride = (size_t)gridDim.x * blockDim.x;
    for (; i < n8; i += stride) {
        float4 a = src[2 * i], b = src[2 * i + 1];
        float f[8] = {a.x, a.y, a.z, a.w, b.x, b.y, b.z, b.w};
        float hv[8], lv[8];
        #pragma unroll
        for (int j = 0; j < 8; ++j) {
            bf16 h, l; split2(f[j], h, l);
            hv[j] = __bfloat162float(h);
            lv[j] = __bfloat162float(l);
        }
        hi[i] = make_uint4(pack2(hv[0], hv[1]), pack2(hv[2], hv[3]),
                           pack2(hv[4], hv[5]), pack2(hv[6], hv[7]));
        lo[i] = make_uint4(pack2(lv[0], lv[1]), pack2(lv[2], lv[3]),
                           pack2(lv[4], lv[5]), pack2(lv[6], lv[7]));
    }
}

// x [8192,256] fp32 -> catA cols [0,256) row-major split, ld=512
__global__ void k_xcat(const float4* __restrict__ x4, bf16* __restrict__ hi,
                       bf16* __restrict__ lo) {
    int idx = blockIdx.x * blockDim.x + threadIdx.x;  // 8192*64
    int row = idx >> 6, c4 = idx & 63;
    float4 v = x4[idx];
    size_t base = (size_t)row * 512 + c4 * 4;
    bf16 h0, h1, h2, h3, l0, l1, l2, l3;
    split2(v.x, h0, l0); split2(v.y, h1, l1);
    split2(v.z, h2, l2); split2(v.w, h3, l3);
    __nv_bfloat162* H = (__nv_bfloat162*)(hi + base);
    __nv_bfloat162* L = (__nv_bfloat162*)(lo + base);
    H[0] = __halves2bfloat162(h0, h1); H[1] = __halves2bfloat162(h2, h3);
    L[0] = __halves2bfloat162(l0, l1); L[1] = __halves2bfloat162(l2, l3);
}

// transpose + split: src [R, C] fp32 -> dst[c][r] split bf16 (dst ld = R)
__global__ void k_tsplit(const float* __restrict__ src, int R, int C,
                         bf16* __restrict__ dhi, bf16* __restrict__ dlo) {
    __shared__ float t[32][33];
    int bx = blockIdx.x * 32;   // col base (over C)
    int by = blockIdx.y * 32;   // row base (over R)
    int tx = threadIdx.x, ty = threadIdx.y;
    #pragma unroll
    for (int i = 0; i < 4; i++)
        t[ty + 8 * i][tx] = src[(size_t)(by + ty + 8 * i) * C + bx + tx];
    __syncthreads();
    #pragma unroll
    for (int i = 0; i < 4; i++) {
        int c = bx + ty + 8 * i;
        float v = t[tx][ty + 8 * i];
        bf16 h, l; split2(v, h, l);
        dhi[(size_t)c * R + by + tx] = h;
        dlo[(size_t)c * R + by + tx] = l;
    }
}

// ---------------- split-bf16 3-product HMMA GEMM (512 threads) ----------------
// C[m0+64, n0+128] = sum_k (Ah+Al)[m,k]*(Bh+Bl)[n,k]   (Al*Bl dropped)
// Stage (48KB): Ah[64][128B]@0, Al@8192, Bh[128][128B]@16384, Bl@32768
// 16 warps: 4(m) x 4(n); per warp m16 x n32.
__device__ __forceinline__ void load_stage(
    uint32_t sb, int stage, int kc,
    const bf16* Ah, const bf16* Al, int lda,
    const bf16* Bh, const bf16* Bl, int ldb,
    int m0, int n0, int tid) {
    uint32_t st = sb + (uint32_t)stage * STAGE_BYTES;
    #pragma unroll
    for (int i = 0; i < 2; ++i) {           // A: 1024 16B chunks
        int g = tid + (i << 9);
        int sub = g >> 9;                   // 0=hi, 1=lo
        int idx = g & 511;
        int row = idx >> 3;
        int cb = (idx & 7) << 4;
        uint32_t dst = st + (uint32_t)(sub * 8192) + (uint32_t)(row * 128)
                     + (uint32_t)(cb ^ ((row & 7) << 4));
        const bf16* srcb = sub ? Al : Ah;
        CP16(dst, (const char*)(srcb + (size_t)(m0 + row) * lda + kc) + cb);
    }
    #pragma unroll
    for (int i = 0; i < 4; ++i) {           // B: 2048 16B chunks
        int g = tid + (i << 9);
        int sub = g >> 10;
        int idx = g & 1023;
        int row = idx >> 3;
        int cb = (idx & 7) << 4;
        uint32_t dst = st + 16384u + (uint32_t)(sub * 16384) + (uint32_t)(row * 128)
                     + (uint32_t)(cb ^ ((row & 7) << 4));
        const bf16* srcb = sub ? Bl : Bh;
        CP16(dst, (const char*)(srcb + (size_t)(n0 + row) * ldb + kc) + cb);
    }
}

__global__ void __launch_bounds__(512, 1)
k_gemm(const bf16* __restrict__ Ah, const bf16* __restrict__ Al, int lda,
       const bf16* __restrict__ Bh, const bf16* __restrict__ Bl, int ldb,
       int K, int mode, int Ncols, const float* __restrict__ bias,
       bf16* __restrict__ orm_hi, bf16* __restrict__ orm_lo, int ld_rm,
       bf16* __restrict__ ot_hi, bf16* __restrict__ ot_lo,
       float* __restrict__ of) {
    extern __shared__ char smem[];
    const int tid = threadIdx.x;
    const uint32_t sb = s2u(smem);
    const int m0 = (int)blockIdx.y * 64;
    const int n0 = (int)blockIdx.x * 128;
    const int lane = tid & 31, wid = tid >> 5;
    const int wm = wid >> 2, wn = wid & 3;          // 4 x 4 warp grid
    const int lg = lane >> 3, lr = lane & 7;

    // ldmatrix lane roles
    const int arow = wm * 16 + (lg & 1) * 8 + lr;
    const uint32_t acol = (uint32_t)((lg >> 1) * 16);
    const uint32_t axr = (uint32_t)((arow & 7) << 4);
    const int brow = wn * 32 + (lg >> 1) * 8 + lr;
    const uint32_t bcol = (uint32_t)((lg & 1) * 16);
    const uint32_t bxr = (uint32_t)((brow & 7) << 4);

    float acc[4][4] = {};
    const int C = K >> 6;

    #pragma unroll
    for (int c = 0; c < 2; ++c) {
        load_stage(sb, c, c << 6, Ah, Al, lda, Bh, Bl, ldb, m0, n0, tid);
        asm volatile("cp.async.commit_group;" ::: "memory");
    }

    for (int c = 0; c < C; ++c) {
        asm volatile("cp.async.wait_group 1;" ::: "memory");
        __syncthreads();
        int nc = c + 2;
        if (nc < C)
            load_stage(sb, nc % 3, nc << 6, Ah, Al, lda, Bh, Bl, ldb, m0, n0, tid);
        asm volatile("cp.async.commit_group;" ::: "memory");

        uint32_t st = sb + (uint32_t)((c % 3) * STAGE_BYTES);
        uint32_t aB = st + (uint32_t)(arow * 128);
        uint32_t bB = st + 16384u + (uint32_t)(brow * 128);
        #pragma unroll
        for (int kq = 0; kq < 4; ++kq) {
            uint32_t ac = ((uint32_t)(kq * 32) + acol) ^ axr;
            uint32_t bc = ((uint32_t)(kq * 32) + bcol) ^ bxr;
            uint32_t ah[4], al[4], bh[2][4], bl[2][4];
            ldsm4(ah, aB + ac);
            ldsm4(al, aB + 8192u + ac);
            ldsm4(bh[0], bB + bc);
            ldsm4(bh[1], bB + 2048u + bc);             // +16 n-rows
            ldsm4(bl[0], bB + 16384u + bc);
            ldsm4(bl[1], bB + 16384u + 2048u + bc);
            #pragma unroll
            for (int ni = 0; ni < 4; ++ni) {
                const uint32_t* bph = &bh[ni >> 1][(ni & 1) * 2];
                const uint32_t* bpl = &bl[ni >> 1][(ni & 1) * 2];
                mma16816(acc[ni], ah, bph);
                mma16816(acc[ni], ah, bpl);
                mma16816(acc[ni], al, bph);
            }
        }
    }

    // ---------------- epilogue ----------------
    {
        int r0 = m0 + wm * 16 + (lane >> 2);
        #pragma unroll
        for (int ni = 0; ni < 4; ++ni) {
            int c = n0 + wn * 32 + ni * 8 + ((lane & 3) << 1);
            float v0 = acc[ni][0], v1 = acc[ni][1];
            float v2 = acc[ni][2], v3 = acc[ni][3];
            if (mode == 2) {
                if (c < Ncols) {
                    float b0v = bias[c], b1v = bias[c + 1];
                    of[(size_t)r0 * Ncols + c]           = v0 + b0v;
                    of[(size_t)r0 * Ncols + c + 1]       = v1 + b1v;
                    of[(size_t)(r0 + 8) * Ncols + c]     = v2 + b0v;
                    of[(size_t)(r0 + 8) * Ncols + c + 1] = v3 + b1v;
                }
            } else {
                if (mode == 1) {
                    float b0v = bias[c], b1v = bias[c + 1];
                    v0 = fmaxf(v0 + b0v, 0.f); v1 = fmaxf(v1 + b1v, 0.f);
                    v2 = fmaxf(v2 + b0v, 0.f); v3 = fmaxf(v3 + b1v, 0.f);
                }
                bf16 h0, l0, h1, l1, h2, l2, h3, l3;
                split2(v0, h0, l0); split2(v1, h1, l1);
                split2(v2, h2, l2); split2(v3, h3, l3);
                *(__nv_bfloat162*)(orm_hi + (size_t)r0 * ld_rm + c) = __halves2bfloat162(h0, h1);
                *(__nv_bfloat162*)(orm_lo + (size_t)r0 * ld_rm + c) = __halves2bfloat162(l0, l1);
                *(__nv_bfloat162*)(orm_hi + (size_t)(r0 + 8) * ld_rm + c) = __halves2bfloat162(h2, h3);
                *(__nv_bfloat162*)(orm_lo + (size_t)(r0 + 8) * ld_rm + c) = __halves2bfloat162(l2, l3);
                if (mode == 1) {
                    ot_hi[(size_t)c * NN + r0] = h0;       ot_lo[(size_t)c * NN + r0] = l0;
                    ot_hi[(size_t)(c + 1) * NN + r0] = h1; ot_lo[(size_t)(c + 1) * NN + r0] = l1;
                    ot_hi[(size_t)c * NN + r0 + 8] = h2;   ot_lo[(size_t)c * NN + r0 + 8] = l2;
                    ot_hi[(size_t)(c + 1) * NN + r0 + 8] = h3;
                    ot_lo[(size_t)(c + 1) * NN + r0 + 8] = l3;
                }
            }
        }
    }
}

// ---------------- host ----------------
static void* symaddr(const void* sym) {
    void* p = nullptr;
    cudaGetSymbolAddress(&p, sym);
    return p;
}

extern "C" void kernel_launch(void* const* d_in, const int* in_sizes, int n_in,
                              void* d_out, int out_size) {
    (void)in_sizes; (void)n_in; (void)out_size;
    const float* x   = (const float*)d_in[0];
    const float* adj = (const float*)d_in[1];
    const float* W1  = (const float*)d_in[2];
    const float* b1  = (const float*)d_in[3];
    const float* W2  = (const float*)d_in[4];
    const float* b2  = (const float*)d_in[5];
    const float* W3  = (const float*)d_in[6];
    const float* b3  = (const float*)d_in[7];
    const float* W4  = (const float*)d_in[8];
    const float* b4  = (const float*)d_in[9];

    bf16* adj_hi  = (bf16*)symaddr(g_adj_hi);
    bf16* adj_lo  = (bf16*)symaddr(g_adj_lo);
    bf16* ht_hi   = (bf16*)symaddr(g_ht_hi);
    bf16* ht_lo   = (bf16*)symaddr(g_ht_lo);
    bf16* catA_hi = (bf16*)symaddr(g_catA_hi);
    bf16* catA_lo = (bf16*)symaddr(g_catA_lo);
    bf16* catB_hi = (bf16*)symaddr(g_catB_hi);
    bf16* catB_lo = (bf16*)symaddr(g_catB_lo);
    bf16* wt_hi   = (bf16*)symaddr(g_wt_hi);
    bf16* wt_lo   = (bf16*)symaddr(g_wt_lo);

    cudaFuncSetAttribute(k_gemm, cudaFuncAttributeMaxDynamicSharedMemorySize, SMEM_BYTES);

    // ---- prep (order chosen so launch #3 = L1 aggregation GEMM for ncu -s 5) ----
    k_split<<<4096, 256>>>((const float4*)adj, (uint4*)adj_hi, (uint4*)adj_lo,
                           (size_t)NN * NN / 8);
    k_xcat<<<2048, 256>>>((const float4*)x, catA_hi, catA_lo);
    k_tsplit<<<dim3(8, 256), dim3(32, 8)>>>(x, NN, 256, ht_hi, ht_lo);          // x^T

    // ---- layer 1 aggregation (profiling target) ----
    k_gemm<<<dim3(2, 128), 512, SMEM_BYTES>>>(adj_hi, adj_lo, NN, ht_hi, ht_lo, NN,
        NN, 0, 256, nullptr, catA_hi + 256, catA_lo + 256, 512, nullptr, nullptr, nullptr);

    // weight transposes (needed only before their linears)
    k_tsplit<<<dim3(4, 16),  dim3(32, 8)>>>(W1, 512, 128, wt_hi,          wt_lo);
    k_tsplit<<<dim3(4, 8),   dim3(32, 8)>>>(W2, 256, 128, wt_hi + 65536,  wt_lo + 65536);
    k_tsplit<<<dim3(4, 8),   dim3(32, 8)>>>(W3, 256, 128, wt_hi + 98304,  wt_lo + 98304);
    k_tsplit<<<dim3(2, 8),   dim3(32, 8)>>>(W4, 256, 64,  wt_hi + 131072, wt_lo + 131072);

    // ---- layer 1 linear ----
    k_gemm<<<dim3(1, 128), 512, SMEM_BYTES>>>(catA_hi, catA_lo, 512, wt_hi, wt_lo, 512,
        512, 1, 128, b1, catB_hi, catB_lo, 256, ht_hi, ht_lo, nullptr);

    // ---- layer 2 ----
    k_gemm<<<dim3(1, 128), 512, SMEM_BYTES>>>(adj_hi, adj_lo, NN, ht_hi, ht_lo, NN,
        NN, 0, 128, nullptr, catB_hi + 128, catB_lo + 128, 256, nullptr, nullptr, nullptr);
    k_gemm<<<dim3(1, 128), 512, SMEM_BYTES>>>(catB_hi, catB_lo, 256,
        wt_hi + 65536, wt_lo + 65536, 256,
        256, 1, 128, b2, catB_hi, catB_lo, 256, ht_hi, ht_lo, nullptr);

    // ---- layer 3 ----
    k_gemm<<<dim3(1, 128), 512, SMEM_BYTES>>>(adj_hi, adj_lo, NN, ht_hi, ht_lo, NN,
        NN, 0, 128, nullptr, catB_hi + 128, catB_lo + 128, 256, nullptr, nullptr, nullptr);
    k_gemm<<<dim3(1, 128), 512, SMEM_BYTES>>>(catB_hi, catB_lo, 256,
        wt_hi + 98304, wt_lo + 98304, 256,
        256, 1, 128, b3, catB_hi, catB_lo, 256, ht_hi, ht_lo, nullptr);

    // ---- layer 4 (fp32 output, N=64 padded to 128 in B) ----
    k_gemm<<<dim3(1, 128), 512, SMEM_BYTES>>>(adj_hi, adj_lo, NN, ht_hi, ht_lo, NN,
        NN, 0, 128, nullptr, catB_hi + 128, catB_lo + 128, 256, nullptr, nullptr, nullptr);
    k_gemm<<<dim3(1, 128), 512, SMEM_BYTES>>>(catB_hi, catB_lo, 256,
        wt_hi + 131072, wt_lo + 131072, 256,
        256, 2, 64, b4, nullptr, nullptr, 0, nullptr, nullptr, (float*)d_out);
}

// round 7
// speedup vs baseline: 1.1518x; 1.1518x over previous
#include <cuda_runtime.h>
#include <cuda_bf16.h>
#include <cstdint>
#include <cstddef>

typedef __nv_bfloat16 bf16;

#define NN 8192
#define STAGE_BYTES 49152u
#define SMEM_BYTES (2 * 49152)

// ---------------- device scratch (no allocs allowed; zero-init at load) ----
__device__ __align__(1024) bf16 g_adj_hi[(size_t)NN * NN];
__device__ __align__(1024) bf16 g_adj_lo[(size_t)NN * NN];
__device__ __align__(1024) bf16 g_ht_hi[256 * NN];           // transposed features [F][NN]
__device__ __align__(1024) bf16 g_ht_lo[256 * NN];
__device__ __align__(1024) bf16 g_catA_hi[(size_t)NN * 512]; // layer1 concat [h|support]
__device__ __align__(1024) bf16 g_catA_lo[(size_t)NN * 512];
__device__ __align__(1024) bf16 g_catB_hi[(size_t)NN * 256]; // layers 2-4 concat
__device__ __align__(1024) bf16 g_catB_lo[(size_t)NN * 256];
__device__ __align__(1024) bf16 g_wt_hi[163840];             // W^T all 4 layers
__device__ __align__(1024) bf16 g_wt_lo[163840];
__device__ __align__(1024) float g_part[4194304];            // split-K partials (16MB)

// ---------------- helpers ----------------
__device__ __forceinline__ uint32_t s2u(const void* p) {
    uint32_t a;
    asm("{ .reg .u64 t; cvta.to.shared.u64 t, %1; cvt.u32.u64 %0, t; }" : "=r"(a) : "l"(p));
    return a;
}

#define CP16(dst_u32, src_ptr) \
    asm volatile("cp.async.cg.shared.global [%0], [%1], 16;" :: "r"(dst_u32), "l"(src_ptr) : "memory")

__device__ __forceinline__ void ldsm4(uint32_t a[4], uint32_t addr) {
    asm volatile("ldmatrix.sync.aligned.m8n8.x4.shared.b16 {%0,%1,%2,%3}, [%4];"
                 : "=r"(a[0]), "=r"(a[1]), "=r"(a[2]), "=r"(a[3]) : "r"(addr));
}

__device__ __forceinline__ void mma16816(float c[4], const uint32_t a[4], const uint32_t b[2]) {
    asm volatile(
        "mma.sync.aligned.m16n8k16.row.col.f32.bf16.bf16.f32 "
        "{%0,%1,%2,%3}, {%4,%5,%6,%7}, {%8,%9}, {%0,%1,%2,%3};"
        : "+f"(c[0]), "+f"(c[1]), "+f"(c[2]), "+f"(c[3])
        : "r"(a[0]), "r"(a[1]), "r"(a[2]), "r"(a[3]), "r"(b[0]), "r"(b[1]));
}

__device__ __forceinline__ void split2(float v, bf16& h, bf16& l) {
    h = __float2bfloat16(v);
    l = __float2bfloat16(v - __bfloat162float(h));
}

__device__ __forceinline__ uint32_t pack2(float a, float b) {
    __nv_bfloat162 p = __halves2bfloat162(__float2bfloat16(a), __float2bfloat16(b));
    return *reinterpret_cast<uint32_t*>(&p);
}

// ---------------- prep kernels ----------------
__global__ void k_split(const float4* __restrict__ src, uint4* __restrict__ hi,
                        uint4* __restrict__ lo, size_t n8) {
    size_t i = (size_t)blockIdx.x * blockDim.x + threadIdx.x;
    size_t stride = (size_t)gridDim.x * blockDim.x;
    for (; i < n8; i += stride) {
        float4 a = src[2 * i], b = src[2 * i + 1];
        float f[8] = {a.x, a.y, a.z, a.w, b.x, b.y, b.z, b.w};
        float hv[8], lv[8];
        #pragma unroll
        for (int j = 0; j < 8; ++j) {
            bf16 h, l; split2(f[j], h, l);
            hv[j] = __bfloat162float(h);
            lv[j] = __bfloat162float(l);
        }
        hi[i] = make_uint4(pack2(hv[0], hv[1]), pack2(hv[2], hv[3]),
                           pack2(hv[4], hv[5]), pack2(hv[6], hv[7]));
        lo[i] = make_uint4(pack2(lv[0], lv[1]), pack2(lv[2], lv[3]),
                           pack2(lv[4], lv[5]), pack2(lv[6], lv[7]));
    }
}

// x [8192,256] fp32 -> catA cols [0,256) row-major split, ld=512
__global__ void k_xcat(const float4* __restrict__ x4, bf16* __restrict__ hi,
                       bf16* __restrict__ lo) {
    int idx = blockIdx.x * blockDim.x + threadIdx.x;  // 8192*64
    int row = idx >> 6, c4 = idx & 63;
    float4 v = x4[idx];
    size_t base = (size_t)row * 512 + c4 * 4;
    bf16 h0, h1, h2, h3, l0, l1, l2, l3;
    split2(v.x, h0, l0); split2(v.y, h1, l1);
    split2(v.z, h2, l2); split2(v.w, h3, l3);
    __nv_bfloat162* H = (__nv_bfloat162*)(hi + base);
    __nv_bfloat162* L = (__nv_bfloat162*)(lo + base);
    H[0] = __halves2bfloat162(h0, h1); H[1] = __halves2bfloat162(h2, h3);
    L[0] = __halves2bfloat162(l0, l1); L[1] = __halves2bfloat162(l2, l3);
}

// transpose + split: src [R, C] fp32 -> dst[c][r] split bf16 (dst ld = R)
__global__ void k_tsplit(const float* __restrict__ src, int R, int C,
                         bf16* __restrict__ dhi, bf16* __restrict__ dlo) {
    __shared__ float t[32][33];
    int bx = blockIdx.x * 32;
    int by = blockIdx.y * 32;
    int tx = threadIdx.x, ty = threadIdx.y;
    #pragma unroll
    for (int i = 0; i < 4; i++)
        t[ty + 8 * i][tx] = src[(size_t)(by + ty + 8 * i) * C + bx + tx];
    __syncthreads();
    #pragma unroll
    for (int i = 0; i < 4; i++) {
        int c = bx + ty + 8 * i;
        float v = t[tx][ty + 8 * i];
        bf16 h, l; split2(v, h, l);
        dhi[(size_t)c * R + by + tx] = h;
        dlo[(size_t)c * R + by + tx] = l;
    }
}

// split-K partial reduce: sum nparts fp32 partials, split-bf16 into cat buffer
__global__ void k_reduce(const float4* __restrict__ p, size_t pstride4, int nparts,
                         bf16* __restrict__ hi, bf16* __restrict__ lo, int F4, int ld) {
    int idx = blockIdx.x * blockDim.x + threadIdx.x;  // 8192*F/4 threads
    int row = idx / F4;
    int c4 = (idx - row * F4) * 4;
    float4 s = p[idx];
    for (int z = 1; z < nparts; ++z) {
        float4 t = p[idx + (size_t)z * pstride4];
        s.x += t.x; s.y += t.y; s.z += t.z; s.w += t.w;
    }
    bf16 h0, l0, h1, l1, h2, l2, h3, l3;
    split2(s.x, h0, l0); split2(s.y, h1, l1);
    split2(s.z, h2, l2); split2(s.w, h3, l3);
    __nv_bfloat162 hA = __halves2bfloat162(h0, h1), hB = __halves2bfloat162(h2, h3);
    __nv_bfloat162 lA = __halves2bfloat162(l0, l1), lB = __halves2bfloat162(l2, l3);
    __nv_bfloat162* H = (__nv_bfloat162*)(hi + (size_t)row * ld + c4);
    __nv_bfloat162* L = (__nv_bfloat162*)(lo + (size_t)row * ld + c4);
    H[0] = hA; H[1] = hB;
    L[0] = lA; L[1] = lB;
}

// ---------------- split-bf16 3-product HMMA GEMM ----------------
// 128 threads, 4 warps (2m x 2n), per-warp m32 x n64. BM=64, BN=128.
// 2 stages x 48KB -> 2 CTAs resident/SM. blockIdx.z = split-K part.
// Stage: Ah[64][128B]@0, Al@8192, Bh[128][128B]@16384, Bl@32768
// mode 1: +bias, relu; split -> orm (ld_rm) AND transposed -> ot (ld NN)
// mode 2: +bias; fp32 -> of (ld Ncols), guard c < Ncols
// mode 3: raw fp32 partial -> of + z*8192*Ncols
__device__ __forceinline__ void load_stage(
    uint32_t sb, int stage, int kc,
    const bf16* Ah, const bf16* Al, int lda,
    const bf16* Bh, const bf16* Bl, int ldb,
    int m0, int n0, int tid) {
    uint32_t st = sb + (uint32_t)stage * STAGE_BYTES;
    #pragma unroll
    for (int i = 0; i < 8; ++i) {           // A: 1024 x 16B (hi+lo)
        int g = tid + (i << 7);
        int sub = g >> 9;                   // 0=hi, 1=lo
        int idx = g & 511;
        int row = idx >> 3;
        int cb = (idx & 7) << 4;
        uint32_t dst = st + (uint32_t)(sub * 8192) + (uint32_t)(row * 128)
                     + (uint32_t)(cb ^ ((row & 7) << 4));
        const bf16* srcb = sub ? Al : Ah;
        CP16(dst, (const char*)(srcb + (size_t)(m0 + row) * lda + kc) + cb);
    }
    #pragma unroll
    for (int i = 0; i < 16; ++i) {          // B: 2048 x 16B (hi+lo)
        int g = tid + (i << 7);
        int sub = g >> 10;
        int idx = g & 1023;
        int row = idx >> 3;
        int cb = (idx & 7) << 4;
        uint32_t dst = st + 16384u + (uint32_t)(sub * 16384) + (uint32_t)(row * 128)
                     + (uint32_t)(cb ^ ((row & 7) << 4));
        const bf16* srcb = sub ? Bl : Bh;
        CP16(dst, (const char*)(srcb + (size_t)(n0 + row) * ldb + cb / 16 * 8 + kc) + (cb & 15));
    }
}

__global__ void __launch_bounds__(128, 2)
k_gemm(const bf16* __restrict__ Ah, const bf16* __restrict__ Al, int lda,
       const bf16* __restrict__ Bh, const bf16* __restrict__ Bl, int ldb,
       int K, int mode, int Ncols, const float* __restrict__ bias,
       bf16* __restrict__ orm_hi, bf16* __restrict__ orm_lo, int ld_rm,
       bf16* __restrict__ ot_hi, bf16* __restrict__ ot_lo,
       float* __restrict__ of) {
    extern __shared__ char smem[];
    const int tid = threadIdx.x;
    const uint32_t sb = s2u(smem);
    const int m0 = (int)blockIdx.y * 64;
    const int n0 = (int)blockIdx.x * 128;
    const int k0 = (int)blockIdx.z * K;
    const int lane = tid & 31, wid = tid >> 5;
    const int wm = wid >> 1, wn = wid & 1;          // 2 x 2 warp grid
    const int lg = lane >> 3, lr = lane & 7;

    const int arow = wm * 32 + (lg & 1) * 8 + lr;
    const uint32_t acol = (uint32_t)((lg >> 1) * 16);
    const uint32_t axr = (uint32_t)((arow & 7) << 4);
    const int brow = wn * 64 + (lg >> 1) * 8 + lr;
    const uint32_t bcol = (uint32_t)((lg & 1) * 16);
    const uint32_t bxr = (uint32_t)((brow & 7) << 4);

    float acc[2][8][4] = {};
    const int C = K >> 6;

    load_stage(sb, 0, k0, Ah, Al, lda, Bh, Bl, ldb, m0, n0, tid);
    asm volatile("cp.async.commit_group;" ::: "memory");
    load_stage(sb, 1, k0 + 64, Ah, Al, lda, Bh, Bl, ldb, m0, n0, tid);
    asm volatile("cp.async.commit_group;" ::: "memory");

    for (int c = 0; c < C; ++c) {
        asm volatile("cp.async.wait_group 1;" ::: "memory");
        __syncthreads();

        uint32_t st = sb + (uint32_t)((c & 1) * STAGE_BYTES);
        uint32_t aB = st + (uint32_t)(arow * 128);
        uint32_t bB = st + 16384u + (uint32_t)(brow * 128);
        #pragma unroll
        for (int kq = 0; kq < 4; ++kq) {
            uint32_t ac = ((uint32_t)(kq * 32) + acol) ^ axr;
            uint32_t bc = ((uint32_t)(kq * 32) + bcol) ^ bxr;
            uint32_t ah[2][4], al[2][4], bh[4][4], bl[4][4];
            #pragma unroll
            for (int mi = 0; mi < 2; ++mi) {
                ldsm4(ah[mi], aB + (uint32_t)(mi * 2048) + ac);
                ldsm4(al[mi], aB + 8192u + (uint32_t)(mi * 2048) + ac);
            }
            #pragma unroll
            for (int j = 0; j < 4; ++j) {
                ldsm4(bh[j], bB + (uint32_t)(j * 2048) + bc);
                ldsm4(bl[j], bB + 16384u + (uint32_t)(j * 2048) + bc);
            }
            // product-major order: same-acc reuse distance = 16 HMMAs
            #pragma unroll
            for (int mi = 0; mi < 2; ++mi)
                #pragma unroll
                for (int ni = 0; ni < 8; ++ni)
                    mma16816(acc[mi][ni], ah[mi], &bh[ni >> 1][(ni & 1) * 2]);
            #pragma unroll
            for (int mi = 0; mi < 2; ++mi)
                #pragma unroll
                for (int ni = 0; ni < 8; ++ni)
                    mma16816(acc[mi][ni], ah[mi], &bl[ni >> 1][(ni & 1) * 2]);
            #pragma unroll
            for (int mi = 0; mi < 2; ++mi)
                #pragma unroll
                for (int ni = 0; ni < 8; ++ni)
                    mma16816(acc[mi][ni], al[mi], &bh[ni >> 1][(ni & 1) * 2]);
        }
        __syncthreads();
        int nc = c + 2;
        if (nc < C)
            load_stage(sb, c & 1, k0 + (nc << 6), Ah, Al, lda, Bh, Bl, ldb, m0, n0, tid);
        asm volatile("cp.async.commit_group;" ::: "memory");
    }

    // ---------------- epilogue ----------------
    if (mode == 3) of += (size_t)blockIdx.z * NN * Ncols;
    #pragma unroll
    for (int mi = 0; mi < 2; ++mi) {
        int r0 = m0 + wm * 32 + mi * 16 + (lane >> 2);
        #pragma unroll
        for (int ni = 0; ni < 8; ++ni) {
            int c = n0 + wn * 64 + ni * 8 + ((lane & 3) << 1);
            float v0 = acc[mi][ni][0], v1 = acc[mi][ni][1];
            float v2 = acc[mi][ni][2], v3 = acc[mi][ni][3];
            if (mode == 3) {
                *(float2*)(of + (size_t)r0 * Ncols + c)       = make_float2(v0, v1);
                *(float2*)(of + (size_t)(r0 + 8) * Ncols + c) = make_float2(v2, v3);
            } else if (mode == 2) {
                if (c < Ncols) {
                    float b0v = bias[c], b1v = bias[c + 1];
                    *(float2*)(of + (size_t)r0 * Ncols + c)       = make_float2(v0 + b0v, v1 + b1v);
                    *(float2*)(of + (size_t)(r0 + 8) * Ncols + c) = make_float2(v2 + b0v, v3 + b1v);
                }
            } else {
                float b0v = bias[c], b1v = bias[c + 1];
                v0 = fmaxf(v0 + b0v, 0.f); v1 = fmaxf(v1 + b1v, 0.f);
                v2 = fmaxf(v2 + b0v, 0.f); v3 = fmaxf(v3 + b1v, 0.f);
                bf16 h0, l0, h1, l1, h2, l2, h3, l3;
                split2(v0, h0, l0); split2(v1, h1, l1);
                split2(v2, h2, l2); split2(v3, h3, l3);
                *(__nv_bfloat162*)(orm_hi + (size_t)r0 * ld_rm + c) = __halves2bfloat162(h0, h1);
                *(__nv_bfloat162*)(orm_lo + (size_t)r0 * ld_rm + c) = __halves2bfloat162(l0, l1);
                *(__nv_bfloat162*)(orm_hi + (size_t)(r0 + 8) * ld_rm + c) = __halves2bfloat162(h2, h3);
                *(__nv_bfloat162*)(orm_lo + (size_t)(r0 + 8) * ld_rm + c) = __halves2bfloat162(l2, l3);
                ot_hi[(size_t)c * NN + r0] = h0;       ot_lo[(size_t)c * NN + r0] = l0;
                ot_hi[(size_t)(c + 1) * NN + r0] = h1; ot_lo[(size_t)(c + 1) * NN + r0] = l1;
                ot_hi[(size_t)c * NN + r0 + 8] = h2;   ot_lo[(size_t)c * NN + r0 + 8] = l2;
                ot_hi[(size_t)(c + 1) * NN + r0 + 8] = h3;
                ot_lo[(size_t)(c + 1) * NN + r0 + 8] = l3;
            }
        }
    }
}

// ---------------- host ----------------
static void* symaddr(const void* sym) {
    void* p = nullptr;
    cudaGetSymbolAddress(&p, sym);
    return p;
}

extern "C" void kernel_launch(void* const* d_in, const int* in_sizes, int n_in,
                              void* d_out, int out_size) {
    (void)in_sizes; (void)n_in; (void)out_size;
    const float* x   = (const float*)d_in[0];
    const float* adj = (const float*)d_in[1];
    const float* W1  = (const float*)d_in[2];
    const float* b1  = (const float*)d_in[3];
    const float* W2  = (const float*)d_in[4];
    const float* b2  = (const float*)d_in[5];
    const float* W3  = (const float*)d_in[6];
    const float* b3  = (const float*)d_in[7];
    const float* W4  = (const float*)d_in[8];
    const float* b4  = (const float*)d_in[9];

    bf16* adj_hi  = (bf16*)symaddr(g_adj_hi);
    bf16* adj_lo  = (bf16*)symaddr(g_adj_lo);
    bf16* ht_hi   = (bf16*)symaddr(g_ht_hi);
    bf16* ht_lo   = (bf16*)symaddr(g_ht_lo);
    bf16* catA_hi = (bf16*)symaddr(g_catA_hi);
    bf16* catA_lo = (bf16*)symaddr(g_catA_lo);
    bf16* catB_hi = (bf16*)symaddr(g_catB_hi);
    bf16* catB_lo = (bf16*)symaddr(g_catB_lo);
    bf16* wt_hi   = (bf16*)symaddr(g_wt_hi);
    bf16* wt_lo   = (bf16*)symaddr(g_wt_lo);
    float* part   = (float*)symaddr(g_part);

    cudaFuncSetAttribute(k_gemm, cudaFuncAttributeMaxDynamicSharedMemorySize, SMEM_BYTES);

    // ---- prep (L1 agg kept as launch #4 = ncu target) ----
    k_split<<<4096, 256>>>((const float4*)adj, (uint4*)adj_hi, (uint4*)adj_lo,
                           (size_t)NN * NN / 8);
    k_xcat<<<2048, 256>>>((const float4*)x, catA_hi, catA_lo);
    k_tsplit<<<dim3(8, 256), dim3(32, 8)>>>(x, NN, 256, ht_hi, ht_lo);

    // ---- layer 1 aggregation: split-K x2, 512 CTAs (profiling target) ----
    k_gemm<<<dim3(2, 128, 2), 128, SMEM_BYTES>>>(adj_hi, adj_lo, NN, ht_hi, ht_lo, NN,
        4096, 3, 256, nullptr, nullptr, nullptr, 0, nullptr, nullptr, part);
    k_reduce<<<2048, 256>>>((const float4*)part, (size_t)NN * 256 / 4, 2,
                            catA_hi + 256, catA_lo + 256, 64, 512);

    k_tsplit<<<dim3(4, 16), dim3(32, 8)>>>(W1, 512, 128, wt_hi,          wt_lo);
    k_tsplit<<<dim3(4, 8),  dim3(32, 8)>>>(W2, 256, 128, wt_hi + 65536,  wt_lo + 65536);
    k_tsplit<<<dim3(4, 8),  dim3(32, 8)>>>(W3, 256, 128, wt_hi + 98304,  wt_lo + 98304);
    k_tsplit<<<dim3(2, 8),  dim3(32, 8)>>>(W4, 256, 64,  wt_hi + 131072, wt_lo + 131072);

    // ---- layer 1 linear ----
    k_gemm<<<dim3(1, 128, 1), 128, SMEM_BYTES>>>(catA_hi, catA_lo, 512, wt_hi, wt_lo, 512,
        512, 1, 128, b1, catB_hi, catB_lo, 256, ht_hi, ht_lo, nullptr);

    // ---- layer 2 ----
    k_gemm<<<dim3(1, 128, 4), 128, SMEM_BYTES>>>(adj_hi, adj_lo, NN, ht_hi, ht_lo, NN,
        2048, 3, 128, nullptr, nullptr, nullptr, 0, nullptr, nullptr, part);
    k_reduce<<<1024, 256>>>((const float4*)part, (size_t)NN * 128 / 4, 4,
                            catB_hi + 128, catB_lo + 128, 32, 256);
    k_gemm<<<dim3(1, 128, 1), 128, SMEM_BYTES>>>(catB_hi, catB_lo, 256,
        wt_hi + 65536, wt_lo + 65536, 256,
        256, 1, 128, b2, catB_hi, catB_lo, 256, ht_hi, ht_lo, nullptr);

    // ---- layer 3 ----
    k_gemm<<<dim3(1, 128, 4), 128, SMEM_BYTES>>>(adj_hi, adj_lo, NN, ht_hi, ht_lo, NN,
        2048, 3, 128, nullptr, nullptr, nullptr, 0, nullptr, nullptr, part);
    k_reduce<<<1024, 256>>>((const float4*)part, (size_t)NN * 128 / 4, 4,
                            catB_hi + 128, catB_lo + 128, 32, 256);
    k_gemm<<<dim3(1, 128, 1), 128, SMEM_BYTES>>>(catB_hi, catB_lo, 256,
        wt_hi + 98304, wt_lo + 98304, 256,
        256, 1, 128, b3, catB_hi, catB_lo, 256, ht_hi, ht_lo, nullptr);

    // ---- layer 4 ----
    k_gemm<<<dim3(1, 128, 4), 128, SMEM_BYTES>>>(adj_hi, adj_lo, NN, ht_hi, ht_lo, NN,
        2048, 3, 128, nullptr, nullptr, nullptr, 0, nullptr, nullptr, part);
    k_reduce<<<1024, 256>>>((const float4*)part, (size_t)NN * 128 / 4, 4,
                            catB_hi + 128, catB_lo + 128, 32, 256);
    k_gemm<<<dim3(1, 128, 1), 128, SMEM_BYTES>>>(catB_hi, catB_lo, 256,
        wt_hi + 131072, wt_lo + 131072, 256,
        256, 2, 64, b4, nullptr, nullptr, 0, nullptr, nullptr, (float*)d_out);
}

// round 8
// speedup vs baseline: 1.2609x; 1.0947x over previous
#include <cuda_runtime.h>
#include <cuda_bf16.h>
#include <cstdint>
#include <cstddef>

typedef __nv_bfloat16 bf16;

#define NN 8192
#define STAGE_BYTES 49152u
#define SMEM_BYTES (2 * 49152)

// ---------------- device scratch (no allocs allowed; zero-init at load) ----
__device__ __align__(1024) bf16 g_adj_hi[(size_t)NN * NN];
__device__ __align__(1024) bf16 g_adj_lo[(size_t)NN * NN];
__device__ __align__(1024) bf16 g_ht_hi[256 * NN];           // transposed features [F][NN]
__device__ __align__(1024) bf16 g_ht_lo[256 * NN];
__device__ __align__(1024) bf16 g_catA_hi[(size_t)NN * 512]; // layer1 concat [h|support]
__device__ __align__(1024) bf16 g_catA_lo[(size_t)NN * 512];
__device__ __align__(1024) bf16 g_catB_hi[(size_t)NN * 256]; // layers 2-4 concat
__device__ __align__(1024) bf16 g_catB_lo[(size_t)NN * 256];
__device__ __align__(1024) bf16 g_wt_hi[163840];             // W^T all 4 layers
__device__ __align__(1024) bf16 g_wt_lo[163840];
__device__ __align__(1024) float g_part[16777216];           // split-K partials (64MB)

// ---------------- helpers ----------------
__device__ __forceinline__ uint32_t s2u(const void* p) {
    uint32_t a;
    asm("{ .reg .u64 t; cvta.to.shared.u64 t, %1; cvt.u32.u64 %0, t; }" : "=r"(a) : "l"(p));
    return a;
}

#define CP16(dst_u32, src_ptr) \
    asm volatile("cp.async.cg.shared.global [%0], [%1], 16;" :: "r"(dst_u32), "l"(src_ptr) : "memory")

__device__ __forceinline__ void ldsm4(uint32_t a[4], uint32_t addr) {
    asm volatile("ldmatrix.sync.aligned.m8n8.x4.shared.b16 {%0,%1,%2,%3}, [%4];"
                 : "=r"(a[0]), "=r"(a[1]), "=r"(a[2]), "=r"(a[3]) : "r"(addr));
}

__device__ __forceinline__ void mma16816(float c[4], const uint32_t a[4], const uint32_t b[2]) {
    asm volatile(
        "mma.sync.aligned.m16n8k16.row.col.f32.bf16.bf16.f32 "
        "{%0,%1,%2,%3}, {%4,%5,%6,%7}, {%8,%9}, {%0,%1,%2,%3};"
        : "+f"(c[0]), "+f"(c[1]), "+f"(c[2]), "+f"(c[3])
        : "r"(a[0]), "r"(a[1]), "r"(a[2]), "r"(a[3]), "r"(b[0]), "r"(b[1]));
}

__device__ __forceinline__ void split2(float v, bf16& h, bf16& l) {
    h = __float2bfloat16(v);
    l = __float2bfloat16(v - __bfloat162float(h));
}

// cvt two fp32 -> packed bf16x2 (hi_el = upper half, lo_el = lower half)
__device__ __forceinline__ uint32_t cvt2(float hi_el, float lo_el) {
    uint32_t r;
    asm("cvt.rn.bf16x2.f32 %0, %1, %2;" : "=r"(r) : "f"(hi_el), "f"(lo_el));
    return r;
}

// ---------------- prep kernels ----------------
// truncation split: hi = top 16 bits of fp32 (exact lo remainder), .cs streaming
__global__ void k_split(const uint4* __restrict__ src, uint4* __restrict__ hi,
                        uint4* __restrict__ lo, size_t n8) {
    size_t i = (size_t)blockIdx.x * blockDim.x + threadIdx.x;
    size_t stride = (size_t)gridDim.x * blockDim.x;
    for (; i < n8; i += stride) {
        uint4 a = __ldcs(src + 2 * i);
        uint4 b = __ldcs(src + 2 * i + 1);
        uint32_t u[8] = {a.x, a.y, a.z, a.w, b.x, b.y, b.z, b.w};
        uint4 H, L;
        H.x = __byte_perm(u[0], u[1], 0x7632);
        H.y = __byte_perm(u[2], u[3], 0x7632);
        H.z = __byte_perm(u[4], u[5], 0x7632);
        H.w = __byte_perm(u[6], u[7], 0x7632);
        float l[8];
        #pragma unroll
        for (int j = 0; j < 8; ++j) {
            float f  = __uint_as_float(u[j]);
            float hf = __uint_as_float(u[j] & 0xffff0000u);
            l[j] = f - hf;
        }
        L.x = cvt2(l[1], l[0]);
        L.y = cvt2(l[3], l[2]);
        L.z = cvt2(l[5], l[4]);
        L.w = cvt2(l[7], l[6]);
        __stcs(hi + i, H);
        __stcs(lo + i, L);
    }
}

// x [8192,256] fp32 -> catA cols [0,256) row-major split, ld=512
__global__ void k_xcat(const float4* __restrict__ x4, bf16* __restrict__ hi,
                       bf16* __restrict__ lo) {
    int idx = blockIdx.x * blockDim.x + threadIdx.x;  // 8192*64
    int row = idx >> 6, c4 = idx & 63;
    float4 v = x4[idx];
    size_t base = (size_t)row * 512 + c4 * 4;
    bf16 h0, h1, h2, h3, l0, l1, l2, l3;
    split2(v.x, h0, l0); split2(v.y, h1, l1);
    split2(v.z, h2, l2); split2(v.w, h3, l3);
    __nv_bfloat162* H = (__nv_bfloat162*)(hi + base);
    __nv_bfloat162* L = (__nv_bfloat162*)(lo + base);
    H[0] = __halves2bfloat162(h0, h1); H[1] = __halves2bfloat162(h2, h3);
    L[0] = __halves2bfloat162(l0, l1); L[1] = __halves2bfloat162(l2, l3);
}

// transpose + split: src [R, C] fp32 -> dst[c][r] split bf16 (dst ld = R)
__global__ void k_tsplit(const float* __restrict__ src, int R, int C,
                         bf16* __restrict__ dhi, bf16* __restrict__ dlo) {
    __shared__ float t[32][33];
    int bx = blockIdx.x * 32;
    int by = blockIdx.y * 32;
    int tx = threadIdx.x, ty = threadIdx.y;
    #pragma unroll
    for (int i = 0; i < 4; i++)
        t[ty + 8 * i][tx] = src[(size_t)(by + ty + 8 * i) * C + bx + tx];
    __syncthreads();
    #pragma unroll
    for (int i = 0; i < 4; i++) {
        int c = bx + ty + 8 * i;
        float v = t[tx][ty + 8 * i];
        bf16 h, l; split2(v, h, l);
        dhi[(size_t)c * R + by + tx] = h;
        dlo[(size_t)c * R + by + tx] = l;
    }
}

// split-K partial reduce: sum nparts fp32 partials, split-bf16 into cat buffer
__global__ void k_reduce(const float4* __restrict__ p, size_t pstride4, int nparts,
                         bf16* __restrict__ hi, bf16* __restrict__ lo, int F4, int ld) {
    int idx = blockIdx.x * blockDim.x + threadIdx.x;
    int row = idx / F4;
    int c4 = (idx - row * F4) * 4;
    float4 s = p[idx];
    for (int z = 1; z < nparts; ++z) {
        float4 t = p[idx + (size_t)z * pstride4];
        s.x += t.x; s.y += t.y; s.z += t.z; s.w += t.w;
    }
    bf16 h0, l0, h1, l1, h2, l2, h3, l3;
    split2(s.x, h0, l0); split2(s.y, h1, l1);
    split2(s.z, h2, l2); split2(s.w, h3, l3);
    __nv_bfloat162* H = (__nv_bfloat162*)(hi + (size_t)row * ld + c4);
    __nv_bfloat162* L = (__nv_bfloat162*)(lo + (size_t)row * ld + c4);
    H[0] = __halves2bfloat162(h0, h1); H[1] = __halves2bfloat162(h2, h3);
    L[0] = __halves2bfloat162(l0, l1); L[1] = __halves2bfloat162(l2, l3);
}

// ---------------- split-bf16 3-product HMMA GEMM ----------------
// 128 threads, 4 warps (2m x 2n), per-warp m32 x n64. BM=64, BN=128.
// 2 stages x 48KB -> 2 CTAs/SM. Split-K via blockIdx.z with uneven chunk ranges.
// Stage: Ah[64][128B]@0, Al@8192, Bh[128][128B]@16384, Bl@32768
__device__ __forceinline__ void load_stage(
    uint32_t sb, int stage, int kc,
    const bf16* Ah, const bf16* Al, int lda,
    const bf16* Bh, const bf16* Bl, int ldb,
    int m0, int n0, int tid) {
    uint32_t st = sb + (uint32_t)stage * STAGE_BYTES;
    #pragma unroll
    for (int i = 0; i < 8; ++i) {           // A: 1024 x 16B (hi+lo)
        int g = tid + (i << 7);
        int sub = g >> 9;
        int idx = g & 511;
        int row = idx >> 3;
        int cb = (idx & 7) << 4;
        uint32_t dst = st + (uint32_t)(sub * 8192) + (uint32_t)(row * 128)
                     + (uint32_t)(cb ^ ((row & 7) << 4));
        const bf16* srcb = sub ? Al : Ah;
        CP16(dst, (const char*)(srcb + (size_t)(m0 + row) * lda + kc) + cb);
    }
    #pragma unroll
    for (int i = 0; i < 16; ++i) {          // B: 2048 x 16B (hi+lo)
        int g = tid + (i << 7);
        int sub = g >> 10;
        int idx = g & 1023;
        int row = idx >> 3;
        int cb = (idx & 7) << 4;
        uint32_t dst = st + 16384u + (uint32_t)(sub * 16384) + (uint32_t)(row * 128)
                     + (uint32_t)(cb ^ ((row & 7) << 4));
        const bf16* srcb = sub ? Bl : Bh;
        CP16(dst, (const char*)(srcb + (size_t)(n0 + row) * ldb + kc) + cb);
    }
}

struct Frags {
    uint32_t ah[2][4], al[2][4], bh[4][4], bl[4][4];
};

__device__ __forceinline__ void frag_load(uint32_t aB, uint32_t bB, int kq,
                                          uint32_t acol, uint32_t axr,
                                          uint32_t bcol, uint32_t bxr, Frags& f) {
    uint32_t ac = ((uint32_t)(kq * 32) + acol) ^ axr;
    uint32_t bc = ((uint32_t)(kq * 32) + bcol) ^ bxr;
    #pragma unroll
    for (int mi = 0; mi < 2; ++mi) {
        ldsm4(f.ah[mi], aB + (uint32_t)(mi * 2048) + ac);
        ldsm4(f.al[mi], aB + 8192u + (uint32_t)(mi * 2048) + ac);
    }
    #pragma unroll
    for (int j = 0; j < 4; ++j) {
        ldsm4(f.bh[j], bB + (uint32_t)(j * 2048) + bc);
        ldsm4(f.bl[j], bB + 16384u + (uint32_t)(j * 2048) + bc);
    }
}

__device__ __forceinline__ void frag_mma(float acc[2][8][4], const Frags& f) {
    #pragma unroll
    for (int mi = 0; mi < 2; ++mi)
        #pragma unroll
        for (int ni = 0; ni < 8; ++ni)
            mma16816(acc[mi][ni], f.ah[mi], &f.bh[ni >> 1][(ni & 1) * 2]);
    #pragma unroll
    for (int mi = 0; mi < 2; ++mi)
        #pragma unroll
        for (int ni = 0; ni < 8; ++ni)
            mma16816(acc[mi][ni], f.ah[mi], &f.bl[ni >> 1][(ni & 1) * 2]);
    #pragma unroll
    for (int mi = 0; mi < 2; ++mi)
        #pragma unroll
        for (int ni = 0; ni < 8; ++ni)
            mma16816(acc[mi][ni], f.al[mi], &f.bh[ni >> 1][(ni & 1) * 2]);
}

__global__ void __launch_bounds__(128, 2)
k_gemm(const bf16* __restrict__ Ah, const bf16* __restrict__ Al, int lda,
       const bf16* __restrict__ Bh, const bf16* __restrict__ Bl, int ldb,
       int K, int mode, int Ncols, const float* __restrict__ bias,
       bf16* __restrict__ orm_hi, bf16* __restrict__ orm_lo, int ld_rm,
       bf16* __restrict__ ot_hi, bf16* __restrict__ ot_lo,
       float* __restrict__ of) {
    extern __shared__ char smem[];
    const int tid = threadIdx.x;
    const uint32_t sb = s2u(smem);
    const int m0 = (int)blockIdx.y * 64;
    const int n0 = (int)blockIdx.x * 128;
    // uneven split-K chunk range
    const int CT = K >> 6;
    const int nz = (int)gridDim.z;
    const int c0 = (int)((size_t)blockIdx.z * CT / nz);
    const int c1 = (int)(((size_t)blockIdx.z + 1) * CT / nz);
    const int lane = tid & 31, wid = tid >> 5;
    const int wm = wid >> 1, wn = wid & 1;
    const int lg = lane >> 3, lr = lane & 7;

    const int arow = wm * 32 + (lg & 1) * 8 + lr;
    const uint32_t acol = (uint32_t)((lg >> 1) * 16);
    const uint32_t axr = (uint32_t)((arow & 7) << 4);
    const int brow = wn * 64 + (lg >> 1) * 8 + lr;
    const uint32_t bcol = (uint32_t)((lg & 1) * 16);
    const uint32_t bxr = (uint32_t)((brow & 7) << 4);

    float acc[2][8][4] = {};

    load_stage(sb, 0, c0 << 6, Ah, Al, lda, Bh, Bl, ldb, m0, n0, tid);
    asm volatile("cp.async.commit_group;" ::: "memory");
    load_stage(sb, 1, (c0 + 1) << 6, Ah, Al, lda, Bh, Bl, ldb, m0, n0, tid);
    asm volatile("cp.async.commit_group;" ::: "memory");

    for (int c = c0; c < c1; ++c) {
        asm volatile("cp.async.wait_group 1;" ::: "memory");
        __syncthreads();

        uint32_t st = sb + (uint32_t)(((c - c0) & 1) * STAGE_BYTES);
        uint32_t aB = st + (uint32_t)(arow * 128);
        uint32_t bB = st + 16384u + (uint32_t)(brow * 128);

        Frags f;
        #pragma unroll
        for (int kq = 0; kq < 3; ++kq) {
            frag_load(aB, bB, kq, acol, axr, bcol, bxr, f);
            frag_mma(acc, f);
        }
        // last kq: fragments to regs, release stage, overlap loads with mma
        frag_load(aB, bB, 3, acol, axr, bcol, bxr, f);
        __syncthreads();
        int nc = c + 2;
        if (nc < c1)
            load_stage(sb, (c - c0) & 1, nc << 6, Ah, Al, lda, Bh, Bl, ldb, m0, n0, tid);
        asm volatile("cp.async.commit_group;" ::: "memory");
        frag_mma(acc, f);
    }

    // ---------------- epilogue ----------------
    if (mode == 3) of += (size_t)blockIdx.z * NN * Ncols;
    #pragma unroll
    for (int mi = 0; mi < 2; ++mi) {
        int r0 = m0 + wm * 32 + mi * 16 + (lane >> 2);
        #pragma unroll
        for (int ni = 0; ni < 8; ++ni) {
            int c = n0 + wn * 64 + ni * 8 + ((lane & 3) << 1);
            float v0 = acc[mi][ni][0], v1 = acc[mi][ni][1];
            float v2 = acc[mi][ni][2], v3 = acc[mi][ni][3];
            if (mode == 3) {
                *(float2*)(of + (size_t)r0 * Ncols + c)       = make_float2(v0, v1);
                *(float2*)(of + (size_t)(r0 + 8) * Ncols + c) = make_float2(v2, v3);
            } else if (mode == 2) {
                if (c < Ncols) {
                    float b0v = bias[c], b1v = bias[c + 1];
                    *(float2*)(of + (size_t)r0 * Ncols + c)       = make_float2(v0 + b0v, v1 + b1v);
                    *(float2*)(of + (size_t)(r0 + 8) * Ncols + c) = make_float2(v2 + b0v, v3 + b1v);
                }
            } else {
                float b0v = bias[c], b1v = bias[c + 1];
                v0 = fmaxf(v0 + b0v, 0.f); v1 = fmaxf(v1 + b1v, 0.f);
                v2 = fmaxf(v2 + b0v, 0.f); v3 = fmaxf(v3 + b1v, 0.f);
                bf16 h0, l0, h1, l1, h2, l2, h3, l3;
                split2(v0, h0, l0); split2(v1, h1, l1);
                split2(v2, h2, l2); split2(v3, h3, l3);
                *(__nv_bfloat162*)(orm_hi + (size_t)r0 * ld_rm + c) = __halves2bfloat162(h0, h1);
                *(__nv_bfloat162*)(orm_lo + (size_t)r0 * ld_rm + c) = __halves2bfloat162(l0, l1);
                *(__nv_bfloat162*)(orm_hi + (size_t)(r0 + 8) * ld_rm + c) = __halves2bfloat162(h2, h3);
                *(__nv_bfloat162*)(orm_lo + (size_t)(r0 + 8) * ld_rm + c) = __halves2bfloat162(l2, l3);
                ot_hi[(size_t)c * NN + r0] = h0;       ot_lo[(size_t)c * NN + r0] = l0;
                ot_hi[(size_t)(c + 1) * NN + r0] = h1; ot_lo[(size_t)(c + 1) * NN + r0] = l1;
                ot_hi[(size_t)c * NN + r0 + 8] = h2;   ot_lo[(size_t)c * NN + r0 + 8] = l2;
                ot_hi[(size_t)(c + 1) * NN + r0 + 8] = h3;
                ot_lo[(size_t)(c + 1) * NN + r0 + 8] = l3;
            }
        }
    }
}

// ---------------- host ----------------
static void* symaddr(const void* sym) {
    void* p = nullptr;
    cudaGetSymbolAddress(&p, sym);
    return p;
}

extern "C" void kernel_launch(void* const* d_in, const int* in_sizes, int n_in,
                              void* d_out, int out_size) {
    (void)in_sizes; (void)n_in; (void)out_size;
    const float* x   = (const float*)d_in[0];
    const float* adj = (const float*)d_in[1];
    const float* W1  = (const float*)d_in[2];
    const float* b1  = (const float*)d_in[3];
    const float* W2  = (const float*)d_in[4];
    const float* b2  = (const float*)d_in[5];
    const float* W3  = (const float*)d_in[6];
    const float* b3  = (const float*)d_in[7];
    const float* W4  = (const float*)d_in[8];
    const float* b4  = (const float*)d_in[9];

    bf16* adj_hi  = (bf16*)symaddr(g_adj_hi);
    bf16* adj_lo  = (bf16*)symaddr(g_adj_lo);
    bf16* ht_hi   = (bf16*)symaddr(g_ht_hi);
    bf16* ht_lo   = (bf16*)symaddr(g_ht_lo);
    bf16* catA_hi = (bf16*)symaddr(g_catA_hi);
    bf16* catA_lo = (bf16*)symaddr(g_catA_lo);
    bf16* catB_hi = (bf16*)symaddr(g_catB_hi);
    bf16* catB_lo = (bf16*)symaddr(g_catB_lo);
    bf16* wt_hi   = (bf16*)symaddr(g_wt_hi);
    bf16* wt_lo   = (bf16*)symaddr(g_wt_lo);
    float* part   = (float*)symaddr(g_part);

    cudaFuncSetAttribute(k_gemm, cudaFuncAttributeMaxDynamicSharedMemorySize, SMEM_BYTES);

    // ---- prep (L1 agg kept as launch #4 = ncu target) ----
    k_split<<<4096, 256>>>((const uint4*)adj, (uint4*)adj_hi, (uint4*)adj_lo,
                           (size_t)NN * NN / 8);
    k_xcat<<<2048, 256>>>((const float4*)x, catA_hi, catA_lo);
    k_tsplit<<<dim3(8, 256), dim3(32, 8)>>>(x, NN, 256, ht_hi, ht_lo);

    // ---- layer 1 aggregation: split-K x2 (profiling target) ----
    k_gemm<<<dim3(2, 128, 2), 128, SMEM_BYTES>>>(adj_hi, adj_lo, NN, ht_hi, ht_lo, NN,
        NN, 3, 256, nullptr, nullptr, nullptr, 0, nullptr, nullptr, part);
    k_reduce<<<2048, 256>>>((const float4*)part, (size_t)NN * 256 / 4, 2,
                            catA_hi + 256, catA_lo + 256, 64, 512);

    k_tsplit<<<dim3(4, 16), dim3(32, 8)>>>(W1, 512, 128, wt_hi,          wt_lo);
    k_tsplit<<<dim3(4, 8),  dim3(32, 8)>>>(W2, 256, 128, wt_hi + 65536,  wt_lo + 65536);
    k_tsplit<<<dim3(4, 8),  dim3(32, 8)>>>(W3, 256, 128, wt_hi + 98304,  wt_lo + 98304);
    k_tsplit<<<dim3(2, 8),  dim3(32, 8)>>>(W4, 256, 64,  wt_hi + 131072, wt_lo + 131072);

    // ---- layer 1 linear ----
    k_gemm<<<dim3(1, 128, 1), 128, SMEM_BYTES>>>(catA_hi, catA_lo, 512, wt_hi, wt_lo, 512,
        512, 1, 128, b1, catB_hi, catB_lo, 256, ht_hi, ht_lo, nullptr);

    // ---- layer 2 ----
    k_gemm<<<dim3(1, 128, 9), 128, SMEM_BYTES>>>(adj_hi, adj_lo, NN, ht_hi, ht_lo, NN,
        NN, 3, 128, nullptr, nullptr, nullptr, 0, nullptr, nullptr, part);
    k_reduce<<<1024, 256>>>((const float4*)part, (size_t)NN * 128 / 4, 9,
                            catB_hi + 128, catB_lo + 128, 32, 256);
    k_gemm<<<dim3(1, 128, 1), 128, SMEM_BYTES>>>(catB_hi, catB_lo, 256,
        wt_hi + 65536, wt_lo + 65536, 256,
        256, 1, 128, b2, catB_hi, catB_lo, 256, ht_hi, ht_lo, nullptr);

    // ---- layer 3 ----
    k_gemm<<<dim3(1, 128, 9), 128, SMEM_BYTES>>>(adj_hi, adj_lo, NN, ht_hi, ht_lo, NN,
        NN, 3, 128, nullptr, nullptr, nullptr, 0, nullptr, nullptr, part);
    k_reduce<<<1024, 256>>>((const float4*)part, (size_t)NN * 128 / 4, 9,
                            catB_hi + 128, catB_lo + 128, 32, 256);
    k_gemm<<<dim3(1, 128, 1), 128, SMEM_BYTES>>>(catB_hi, catB_lo, 256,
        wt_hi + 98304, wt_lo + 98304, 256,
        256, 1, 128, b3, catB_hi, catB_lo, 256, ht_hi, ht_lo, nullptr);

    // ---- layer 4 ----
    k_gemm<<<dim3(1, 128, 9), 128, SMEM_BYTES>>>(adj_hi, adj_lo, NN, ht_hi, ht_lo, NN,
        NN, 3, 128, nullptr, nullptr, nullptr, 0, nullptr, nullptr, part);
    k_reduce<<<1024, 256>>>((const float4*)part, (size_t)NN * 128 / 4, 9,
                            catB_hi + 128, catB_lo + 128, 32, 256);
    k_gemm<<<dim3(1, 128, 1), 128, SMEM_BYTES>>>(catB_hi, catB_lo, 256,
        wt_hi + 131072, wt_lo + 131072, 256,
        256, 2, 64, b4, nullptr, nullptr, 0, nullptr, nullptr, (float*)d_out);
}